// round 16
// baseline (speedup 1.0000x reference)
#include <cuda_runtime.h>
#include <cuda_bf16.h>

// Segment-wise mean(|diff|): x flattened is [num_segs, L] contiguous.
// out[g] = mean_{i=0..L-2} |x[g*L+i+1] - x[g*L+i]|
//
// One warp per segment, double-buffered BATCH=4 pipeline, .cs demand loads,
// L2 prefetch prologue. Critical-path ordering, step 3: batches 0,1,2 demand
// loads all issue BEFORE the prefetch prologue (12 LDG.128 = 6 KB in flight
// at warp start); prologue covers lines 48+ only. First two pipeline
// iterations peeled; steady-state loop from b=3 unchanged.

#define BATCH 4

__global__ __launch_bounds__(256) void seg_warp_pipe_kernel(
    const float* __restrict__ x,
    float* __restrict__ out,
    int n4,         // float4s per segment (L/4), multiple of 128
    int nbatches,   // n4 / (32*BATCH), >= 3
    float inv,      // 1/(L-1)
    int num_segs)
{
    const int gwarp = (blockIdx.x * 256 + threadIdx.x) >> 5;
    const int lane  = threadIdx.x & 31;
    if (gwarp >= num_segs) return;

    const float4* __restrict__ pseg =
        reinterpret_cast<const float4*>(x) + (long long)gwarp * n4;
    const float4* __restrict__ p4 = pseg + lane;

    // Batches 0,1,2 demand loads FIRST: 12 independent LDG.128 in flight
    // before any other instructions consume issue slots.
    float4 buf[BATCH], nb1[BATCH], nb2[BATCH];
    #pragma unroll
    for (int i = 0; i < BATCH; i++)
        buf[i] = __ldcs(p4 + i * 32);
    #pragma unroll
    for (int i = 0; i < BATCH; i++)
        nb1[i] = __ldcs(p4 + (BATCH * 32) + i * 32);
    #pragma unroll
    for (int i = 0; i < BATCH; i++)
        nb2[i] = __ldcs(p4 + (2 * BATCH * 32) + i * 32);

    // L2 prefetch prologue: lines 48..nlines-1 (batches 3..N-1), issued
    // while the 12 demand loads are in flight. Register-free MLP; prefetched
    // lines keep default L2 priority, .cs demand loads stream evict-first.
    {
        const char* base = reinterpret_cast<const char*>(pseg);
        const int nlines = n4 >> 3;
        for (int ln = 48 + lane; ln < nlines; ln += 32) {
            asm volatile("prefetch.global.L2 [%0];" :: "l"(base + (long long)ln * 128));
        }
    }

    float sum = 0.0f;

    // Peeled: compute batch 0 (junction -> nb1[0].x).
    #pragma unroll
    for (int i = 0; i < BATCH; i++) {
        const float nextx = (i < BATCH - 1) ? buf[i + 1].x : nb1[0].x;
        const float src = (lane == 0) ? nextx : buf[i].x;
        const float nx  = __shfl_sync(0xFFFFFFFFu, src, (lane + 1) & 31);
        sum += fabsf(buf[i].y - buf[i].x) + fabsf(buf[i].z - buf[i].y)
             + fabsf(buf[i].w - buf[i].z) + fabsf(nx - buf[i].w);
    }

    // Peeled: compute batch 1 (junction -> nb2[0].x).
    #pragma unroll
    for (int i = 0; i < BATCH; i++) {
        const float nextx = (i < BATCH - 1) ? nb1[i + 1].x : nb2[0].x;
        const float src = (lane == 0) ? nextx : nb1[i].x;
        const float nx  = __shfl_sync(0xFFFFFFFFu, src, (lane + 1) & 31);
        sum += fabsf(nb1[i].y - nb1[i].x) + fabsf(nb1[i].z - nb1[i].y)
             + fabsf(nb1[i].w - nb1[i].z) + fabsf(nx - nb1[i].w);
    }
    #pragma unroll
    for (int i = 0; i < BATCH; i++) buf[i] = nb2[i];

    // Steady state: load batch b, compute batch b-1.
    for (int b = 3; b < nbatches; b++) {
        float4 nb[BATCH];
        const float4* q = p4 + b * (BATCH * 32);
        #pragma unroll
        for (int i = 0; i < BATCH; i++)
            nb[i] = __ldcs(q + i * 32);

        #pragma unroll
        for (int i = 0; i < BATCH; i++) {
            const float nextx = (i < BATCH - 1) ? buf[i + 1].x : nb[0].x;
            const float src = (lane == 0) ? nextx : buf[i].x;
            const float nx  = __shfl_sync(0xFFFFFFFFu, src, (lane + 1) & 31);
            sum += fabsf(buf[i].y - buf[i].x) + fabsf(buf[i].z - buf[i].y)
                 + fabsf(buf[i].w - buf[i].z) + fabsf(nx - buf[i].w);
        }
        #pragma unroll
        for (int i = 0; i < BATCH; i++) buf[i] = nb[i];
    }

    // Final batch: last chunk's lane 31 has no successor (segment end).
    #pragma unroll
    for (int i = 0; i < BATCH; i++) {
        const float nextx = (i < BATCH - 1) ? buf[i + 1].x : buf[i].x;
        const float src = (lane == 0) ? nextx : buf[i].x;
        float nx = __shfl_sync(0xFFFFFFFFu, src, (lane + 1) & 31);
        if (i == BATCH - 1 && lane == 31) nx = buf[i].w;  // zero contribution
        sum += fabsf(buf[i].y - buf[i].x) + fabsf(buf[i].z - buf[i].y)
             + fabsf(buf[i].w - buf[i].z) + fabsf(nx - buf[i].w);
    }

    // Warp reduction, lane 0 writes segment mean.
    #pragma unroll
    for (int off = 16; off > 0; off >>= 1)
        sum += __shfl_down_sync(0xFFFFFFFFu, sum, off);
    if (lane == 0)
        out[gwarp] = sum * inv;
}

// Mid path: warp per segment, simple loop (L multiple of 128 floats).
__global__ __launch_bounds__(256) void seg_warp_kernel(
    const float* __restrict__ x,
    float* __restrict__ out,
    int n4, int nchunks, float inv, int num_segs)
{
    const int gwarp = (blockIdx.x * 256 + threadIdx.x) >> 5;
    const int lane  = threadIdx.x & 31;
    if (gwarp >= num_segs) return;

    const float4* __restrict__ p4 =
        reinterpret_cast<const float4*>(x) + (long long)gwarp * n4;

    float sum = 0.0f;
    float4 v = __ldg(p4 + lane);

    #pragma unroll 4
    for (int c = 1; c < nchunks; c++) {
        float4 nv = __ldg(p4 + c * 32 + lane);
        float src = (lane == 0) ? nv.x : v.x;
        float nx  = __shfl_sync(0xFFFFFFFFu, src, (lane + 1) & 31);
        sum += fabsf(v.y - v.x) + fabsf(v.z - v.y)
             + fabsf(v.w - v.z) + fabsf(nx  - v.w);
        v = nv;
    }
    {
        float nx = __shfl_sync(0xFFFFFFFFu, v.x, (lane + 1) & 31);
        if (lane == 31) nx = v.w;
        sum += fabsf(v.y - v.x) + fabsf(v.z - v.y)
             + fabsf(v.w - v.z) + fabsf(nx  - v.w);
    }

    #pragma unroll
    for (int off = 16; off > 0; off >>= 1)
        sum += __shfl_down_sync(0xFFFFFFFFu, sum, off);
    if (lane == 0)
        out[gwarp] = sum * inv;
}

// Generic fallback: one CTA per segment, scalar loads (any L >= 2).
__global__ __launch_bounds__(256) void seg_generic_kernel(
    const float* __restrict__ x,
    float* __restrict__ out,
    int L, float inv)
{
    const long long seg = blockIdx.x;
    const float* __restrict__ p = x + seg * (long long)L;
    const int tid = threadIdx.x;

    float sum = 0.0f;
    for (int i = tid; i < L - 1; i += blockDim.x)
        sum += fabsf(__ldg(p + i + 1) - __ldg(p + i));

    #pragma unroll
    for (int off = 16; off > 0; off >>= 1)
        sum += __shfl_down_sync(0xFFFFFFFFu, sum, off);

    __shared__ float wsum[8];
    const int lane = tid & 31, wid = tid >> 5;
    if (lane == 0) wsum[wid] = sum;
    __syncthreads();
    if (wid == 0) {
        float s = (lane < 8) ? wsum[lane] : 0.0f;
        #pragma unroll
        for (int off = 4; off > 0; off >>= 1)
            s += __shfl_down_sync(0xFFFFFFFFu, s, off);
        if (lane == 0) out[seg] = s * inv;
    }
}

extern "C" void kernel_launch(void* const* d_in, const int* in_sizes, int n_in,
                              void* d_out, int out_size)
{
    const float* x = (const float*)d_in[0];
    float* out = (float*)d_out;

    const long long total = (long long)in_sizes[0];
    const int num_segs = out_size;                     // B * target_len
    const int L = (int)(total / (long long)num_segs);  // segment length
    const float inv = 1.0f / (float)(L - 1);

    const int ctas = (num_segs * 32 + 255) / 256;

    if ((L % (BATCH * 128)) == 0 && L / (BATCH * 128) >= 3) {
        const int n4 = L >> 2;
        const int nbatches = n4 / (BATCH * 32);
        seg_warp_pipe_kernel<<<ctas, 256>>>(x, out, n4, nbatches, inv, num_segs);
    } else if ((L & 127) == 0) {
        const int n4 = L >> 2;
        seg_warp_kernel<<<ctas, 256>>>(x, out, n4, n4 >> 5, inv, num_segs);
    } else {
        seg_generic_kernel<<<num_segs, 256>>>(x, out, L, inv);
    }
}

// round 17
// speedup vs baseline: 1.1034x; 1.1034x over previous
#include <cuda_runtime.h>
#include <cuda_bf16.h>

// Segment-wise mean(|diff|): x flattened is [num_segs, L] contiguous.
// out[g] = mean_{i=0..L-2} |x[g*L+i+1] - x[g*L+i]|
//
// FINAL (R15, best of session: 35.3us = ~7.6 TB/s effective, 95% of HBM
// spec). One warp per segment, double-buffered BATCH=4 pipeline, .cs
// (evict-first) demand loads, L2 prefetch prologue. Critical-path ordering:
// batch-0 AND batch-1 demand loads issue BEFORE the prefetch prologue
// (8 LDG.128 = 4 KB in flight at warp start); prologue covers lines 32+
// only. First pipeline iteration peeled; steady-state loop unchanged.
// Probed and rejected: deeper hoisting (regs/occ cliff), evict-last L2
// partitioning, cp.async.bulk smem ring, 2 segments/warp, cross-wave
// prefetch — all regressed.

#define BATCH 4

__global__ __launch_bounds__(256) void seg_warp_pipe_kernel(
    const float* __restrict__ x,
    float* __restrict__ out,
    int n4,         // float4s per segment (L/4), multiple of 128
    int nbatches,   // n4 / (32*BATCH), >= 2
    float inv,      // 1/(L-1)
    int num_segs)
{
    const int gwarp = (blockIdx.x * 256 + threadIdx.x) >> 5;
    const int lane  = threadIdx.x & 31;
    if (gwarp >= num_segs) return;

    const float4* __restrict__ pseg =
        reinterpret_cast<const float4*>(x) + (long long)gwarp * n4;
    const float4* __restrict__ p4 = pseg + lane;

    // Batch-0 and batch-1 demand loads FIRST: 8 independent LDG.128 in
    // flight before any prefetch instructions consume issue slots.
    float4 buf[BATCH];
    #pragma unroll
    for (int i = 0; i < BATCH; i++)
        buf[i] = __ldcs(p4 + i * 32);

    float4 nbuf[BATCH];
    #pragma unroll
    for (int i = 0; i < BATCH; i++)
        nbuf[i] = __ldcs(p4 + (BATCH * 32) + i * 32);

    // L2 prefetch prologue: lines 32..nlines-1 (batches 2..N-1), issued
    // while the 8 demand loads are in flight. Register-free MLP; prefetched
    // lines keep default L2 priority while .cs demand loads stream
    // evict-first.
    {
        const char* base = reinterpret_cast<const char*>(pseg);
        const int nlines = n4 >> 3;
        for (int ln = 32 + lane; ln < nlines; ln += 32) {
            asm volatile("prefetch.global.L2 [%0];" :: "l"(base + (long long)ln * 128));
        }
    }

    float sum = 0.0f;

    // Peeled iteration b=1: compute batch 0 (nbuf = batch 1 already loaded).
    #pragma unroll
    for (int i = 0; i < BATCH; i++) {
        const float nextx = (i < BATCH - 1) ? buf[i + 1].x : nbuf[0].x;
        const float src = (lane == 0) ? nextx : buf[i].x;
        const float nx  = __shfl_sync(0xFFFFFFFFu, src, (lane + 1) & 31);
        sum += fabsf(buf[i].y - buf[i].x) + fabsf(buf[i].z - buf[i].y)
             + fabsf(buf[i].w - buf[i].z) + fabsf(nx - buf[i].w);
    }
    #pragma unroll
    for (int i = 0; i < BATCH; i++) buf[i] = nbuf[i];

    // Steady state: load batch b, compute batch b-1.
    for (int b = 2; b < nbatches; b++) {
        float4 nb[BATCH];
        const float4* q = p4 + b * (BATCH * 32);
        #pragma unroll
        for (int i = 0; i < BATCH; i++)
            nb[i] = __ldcs(q + i * 32);

        #pragma unroll
        for (int i = 0; i < BATCH; i++) {
            const float nextx = (i < BATCH - 1) ? buf[i + 1].x : nb[0].x;
            const float src = (lane == 0) ? nextx : buf[i].x;
            const float nx  = __shfl_sync(0xFFFFFFFFu, src, (lane + 1) & 31);
            sum += fabsf(buf[i].y - buf[i].x) + fabsf(buf[i].z - buf[i].y)
                 + fabsf(buf[i].w - buf[i].z) + fabsf(nx - buf[i].w);
        }
        #pragma unroll
        for (int i = 0; i < BATCH; i++) buf[i] = nb[i];
    }

    // Final batch: last chunk's lane 31 has no successor (segment end).
    #pragma unroll
    for (int i = 0; i < BATCH; i++) {
        const float nextx = (i < BATCH - 1) ? buf[i + 1].x : buf[i].x;
        const float src = (lane == 0) ? nextx : buf[i].x;
        float nx = __shfl_sync(0xFFFFFFFFu, src, (lane + 1) & 31);
        if (i == BATCH - 1 && lane == 31) nx = buf[i].w;  // zero contribution
        sum += fabsf(buf[i].y - buf[i].x) + fabsf(buf[i].z - buf[i].y)
             + fabsf(buf[i].w - buf[i].z) + fabsf(nx - buf[i].w);
    }

    // Warp reduction, lane 0 writes segment mean.
    #pragma unroll
    for (int off = 16; off > 0; off >>= 1)
        sum += __shfl_down_sync(0xFFFFFFFFu, sum, off);
    if (lane == 0)
        out[gwarp] = sum * inv;
}

// Mid path: warp per segment, simple loop (L multiple of 128 floats).
__global__ __launch_bounds__(256) void seg_warp_kernel(
    const float* __restrict__ x,
    float* __restrict__ out,
    int n4, int nchunks, float inv, int num_segs)
{
    const int gwarp = (blockIdx.x * 256 + threadIdx.x) >> 5;
    const int lane  = threadIdx.x & 31;
    if (gwarp >= num_segs) return;

    const float4* __restrict__ p4 =
        reinterpret_cast<const float4*>(x) + (long long)gwarp * n4;

    float sum = 0.0f;
    float4 v = __ldg(p4 + lane);

    #pragma unroll 4
    for (int c = 1; c < nchunks; c++) {
        float4 nv = __ldg(p4 + c * 32 + lane);
        float src = (lane == 0) ? nv.x : v.x;
        float nx  = __shfl_sync(0xFFFFFFFFu, src, (lane + 1) & 31);
        sum += fabsf(v.y - v.x) + fabsf(v.z - v.y)
             + fabsf(v.w - v.z) + fabsf(nx  - v.w);
        v = nv;
    }
    {
        float nx = __shfl_sync(0xFFFFFFFFu, v.x, (lane + 1) & 31);
        if (lane == 31) nx = v.w;
        sum += fabsf(v.y - v.x) + fabsf(v.z - v.y)
             + fabsf(v.w - v.z) + fabsf(nx  - v.w);
    }

    #pragma unroll
    for (int off = 16; off > 0; off >>= 1)
        sum += __shfl_down_sync(0xFFFFFFFFu, sum, off);
    if (lane == 0)
        out[gwarp] = sum * inv;
}

// Generic fallback: one CTA per segment, scalar loads (any L >= 2).
__global__ __launch_bounds__(256) void seg_generic_kernel(
    const float* __restrict__ x,
    float* __restrict__ out,
    int L, float inv)
{
    const long long seg = blockIdx.x;
    const float* __restrict__ p = x + seg * (long long)L;
    const int tid = threadIdx.x;

    float sum = 0.0f;
    for (int i = tid; i < L - 1; i += blockDim.x)
        sum += fabsf(__ldg(p + i + 1) - __ldg(p + i));

    #pragma unroll
    for (int off = 16; off > 0; off >>= 1)
        sum += __shfl_down_sync(0xFFFFFFFFu, sum, off);

    __shared__ float wsum[8];
    const int lane = tid & 31, wid = tid >> 5;
    if (lane == 0) wsum[wid] = sum;
    __syncthreads();
    if (wid == 0) {
        float s = (lane < 8) ? wsum[lane] : 0.0f;
        #pragma unroll
        for (int off = 4; off > 0; off >>= 1)
            s += __shfl_down_sync(0xFFFFFFFFu, s, off);
        if (lane == 0) out[seg] = s * inv;
    }
}

extern "C" void kernel_launch(void* const* d_in, const int* in_sizes, int n_in,
                              void* d_out, int out_size)
{
    const float* x = (const float*)d_in[0];
    float* out = (float*)d_out;

    const long long total = (long long)in_sizes[0];
    const int num_segs = out_size;                     // B * target_len
    const int L = (int)(total / (long long)num_segs);  // segment length
    const float inv = 1.0f / (float)(L - 1);

    const int ctas = (num_segs * 32 + 255) / 256;

    if ((L % (BATCH * 128)) == 0 && L / (BATCH * 128) >= 3) {
        const int n4 = L >> 2;
        const int nbatches = n4 / (BATCH * 32);
        seg_warp_pipe_kernel<<<ctas, 256>>>(x, out, n4, nbatches, inv, num_segs);
    } else if ((L & 127) == 0) {
        const int n4 = L >> 2;
        seg_warp_kernel<<<ctas, 256>>>(x, out, n4, n4 >> 5, inv, num_segs);
    } else {
        seg_generic_kernel<<<num_segs, 256>>>(x, out, L, inv);
    }
}